// round 2
// baseline (speedup 1.0000x reference)
#include <cuda_runtime.h>
#include <cstdint>
#include <cstddef>

// Problem constants
#define BB   4
#define NN_  4096
#define HH   8
#define DD   64
#define MM   256      // landmarks
#define LL   16       // tokens per landmark
#define BH   32       // BB*HH
#define KERN 33

// ---------------- scratch (device globals; no allocation allowed) -----------
__device__ float g_QL[BH * MM * DD];        // scaled q landmarks
__device__ float g_KL[BH * MM * DD];        // k landmarks
__device__ float g_X [BH * MM * MM];        // attn2 (softmaxed)
__device__ float g_ZA[BH * MM * MM];
__device__ float g_ZB[BH * MM * MM];
__device__ float g_XZ[BH * MM * MM];
__device__ float g_T2[BH * MM * MM];
__device__ float g_T3[BH * MM * MM];
__device__ float g_S [BH * (size_t)NN_ * MM]; // shared score buffer (attn3 then attn1)
__device__ float g_G [BH * MM * DD];        // attn3 @ v
__device__ float g_W [BH * MM * DD];        // z @ (attn3 @ v)
__device__ float g_OA[BH * (size_t)NN_ * DD]; // attn1 @ W
__device__ float g_scal[2];                 // global colsum max, rowsum max

// ---------------- landmarks --------------------------------------------------
__global__ void landmarks_k(const float* __restrict__ q, const float* __restrict__ k)
{
    int bh = blockIdx.y, i = blockIdx.x, d = threadIdx.x;
    int b = bh >> 3, h = bh & 7;
    float sq = 0.f, sk = 0.f;
    #pragma unroll
    for (int j = 0; j < LL; j++) {
        size_t idx = (((size_t)b * NN_ + (size_t)i * LL + j) * HH + h) * DD + d;
        sq += q[idx];
        sk += k[idx];
    }
    size_t o = ((size_t)bh * MM + i) * DD + d;
    g_QL[o] = sq * (0.125f / (float)LL);   // includes d^-0.5 scale
    g_KL[o] = sk * (1.0f  / (float)LL);
}

// ---------------- generic batched GEMM --------------------------------------
// C[bh] = alpha * A[bh] @ op(B[bh]) + beta * E[bh]   (E optional, same shape as C)
// All of M,N multiples of 64; K multiple of 16. Batch addressing: bh -> (b,h),
// offset = b*so + h*si for each operand (lets us address raw (b,n,h,d) tensors).
template<bool TB>
__global__ void gemm_k(const float* __restrict__ A, size_t a_so, size_t a_si, int lda,
                       const float* __restrict__ B, size_t b_so, size_t b_si, int ldb,
                       float* __restrict__ C, size_t c_so, size_t c_si, int ldc,
                       const float* __restrict__ E, size_t e_so, size_t e_si, int lde,
                       int K, float alpha, float beta)
{
    const int bh = blockIdx.z, b = bh >> 3, h = bh & 7;
    A += (size_t)b * a_so + (size_t)h * a_si;
    B += (size_t)b * b_so + (size_t)h * b_si;
    C += (size_t)b * c_so + (size_t)h * c_si;
    if (E) E += (size_t)b * e_so + (size_t)h * e_si;

    __shared__ float As[16][68];
    __shared__ float Bs[16][68];

    const int tid = threadIdx.x;
    const int tx = tid & 15, ty = tid >> 4;
    const int m0 = blockIdx.y * 64, n0 = blockIdx.x * 64;

    float acc[4][4] = {};

    for (int k0 = 0; k0 < K; k0 += 16) {
        #pragma unroll
        for (int i = 0; i < 4; i++) {
            int idx = tid + i * 256;
            int m = idx >> 4, kk = idx & 15;
            As[kk][m] = A[(size_t)(m0 + m) * lda + (k0 + kk)];
        }
        if (TB) {
            #pragma unroll
            for (int i = 0; i < 4; i++) {
                int idx = tid + i * 256;
                int n = idx >> 4, kk = idx & 15;
                Bs[kk][n] = B[(size_t)(n0 + n) * ldb + (k0 + kk)];
            }
        } else {
            #pragma unroll
            for (int i = 0; i < 4; i++) {
                int idx = tid + i * 256;
                int kk = idx >> 6, n = idx & 63;
                Bs[kk][n] = B[(size_t)(k0 + kk) * ldb + (n0 + n)];
            }
        }
        __syncthreads();
        #pragma unroll
        for (int kk = 0; kk < 16; kk++) {
            float a[4], bb[4];
            #pragma unroll
            for (int i = 0; i < 4; i++) a[i] = As[kk][ty * 4 + i];
            #pragma unroll
            for (int j = 0; j < 4; j++) bb[j] = Bs[kk][tx * 4 + j];
            #pragma unroll
            for (int i = 0; i < 4; i++)
                #pragma unroll
                for (int j = 0; j < 4; j++)
                    acc[i][j] += a[i] * bb[j];
        }
        __syncthreads();
    }

    #pragma unroll
    for (int i = 0; i < 4; i++) {
        int m = m0 + ty * 4 + i;
        #pragma unroll
        for (int j = 0; j < 4; j++) {
            int n = n0 + tx * 4 + j;
            float v = alpha * acc[i][j];
            if (E) v += beta * E[(size_t)m * lde + n];
            C[(size_t)m * ldc + n] = v;
        }
    }
}

// ---------------- row softmax (in place) -------------------------------------
__global__ void softmax_rows_k(float* __restrict__ X, int C)
{
    float* row = X + (size_t)blockIdx.x * C;
    __shared__ float red[256];
    int t = threadIdx.x;

    float mx = -1e30f;
    for (int j = t; j < C; j += 256) mx = fmaxf(mx, row[j]);
    red[t] = mx; __syncthreads();
    for (int s = 128; s > 0; s >>= 1) { if (t < s) red[t] = fmaxf(red[t], red[t + s]); __syncthreads(); }
    mx = red[0];
    __syncthreads();

    float sum = 0.f;
    for (int j = t; j < C; j += 256) { float e = expf(row[j] - mx); row[j] = e; sum += e; }
    red[t] = sum; __syncthreads();
    for (int s = 128; s > 0; s >>= 1) { if (t < s) red[t] += red[t + s]; __syncthreads(); }
    float inv = 1.0f / red[0];
    for (int j = t; j < C; j += 256) row[j] *= inv;
}

// ---------------- pinv init: scaling reductions + transposed init ------------
__global__ void zero_scal_k() { if (threadIdx.x < 2) g_scal[threadIdx.x] = 0.f; }

__global__ void colrow_max_k(const float* __restrict__ X)
{
    int bh = blockIdx.x, t = threadIdx.x;
    const float* xb = X + (size_t)bh * MM * MM;
    float cs = 0.f, rs = 0.f;
    for (int i = 0; i < MM; i++) cs += xb[(size_t)i * MM + t];  // column-sum (col t)
    for (int j = 0; j < MM; j++) rs += xb[(size_t)t * MM + j];  // row-sum (row t)
    __shared__ float rc[256], rr[256];
    rc[t] = cs; rr[t] = rs; __syncthreads();
    for (int s = 128; s > 0; s >>= 1) {
        if (t < s) { rc[t] = fmaxf(rc[t], rc[t + s]); rr[t] = fmaxf(rr[t], rr[t + s]); }
        __syncthreads();
    }
    if (t == 0) {  // all values positive -> int compare equals float compare
        atomicMax((int*)&g_scal[0], __float_as_int(rc[0]));
        atomicMax((int*)&g_scal[1], __float_as_int(rr[0]));
    }
}

__global__ void z0_k(const float* __restrict__ X, float* __restrict__ Z)
{
    __shared__ float tile[32][33];
    int bh = blockIdx.z;
    const float* xb = X + (size_t)bh * MM * MM;
    float* zb = Z + (size_t)bh * MM * MM;
    int i0 = blockIdx.x * 32, j0 = blockIdx.y * 32;
    tile[threadIdx.y][threadIdx.x] = xb[(size_t)(j0 + threadIdx.y) * MM + (i0 + threadIdx.x)];
    __syncthreads();
    float inv = 1.0f / (g_scal[0] * g_scal[1]);
    zb[(size_t)(i0 + threadIdx.y) * MM + (j0 + threadIdx.x)] = tile[threadIdx.x][threadIdx.y] * inv;
}

// ---------------- epilogue: depthwise conv residual + transpose --------------
__global__ void epilogue_k(const float* __restrict__ v, const float* __restrict__ rw,
                           const float* __restrict__ OA, float* __restrict__ out)
{
    __shared__ float w[HH * KERN];
    int t = threadIdx.x;
    if (t < HH * KERN) w[t] = rw[t];
    __syncthreads();

    int i = blockIdx.x, b = blockIdx.y;
    int h = t >> 6, d = t & 63;
    int bh = b * HH + h;

    float acc = OA[((size_t)bh * NN_ + i) * DD + d];
    #pragma unroll
    for (int tt = 0; tt < KERN; tt++) {
        int ii = i + tt - KERN / 2;
        if (ii >= 0 && ii < NN_)
            acc += v[(((size_t)b * NN_ + ii) * HH + h) * DD + d] * w[h * KERN + tt];
    }
    out[(((size_t)b * NN_ + i) * HH + h) * DD + d] = acc;
}

// ---------------- host orchestration -----------------------------------------
static void gemm(bool tb,
                 const float* A, size_t aso, size_t asi, int lda,
                 const float* B, size_t bso, size_t bsi, int ldb,
                 float* C, size_t cso, size_t csi, int ldc,
                 const float* E, size_t eso, size_t esi, int lde,
                 int M, int N, int K, float alpha, float beta)
{
    dim3 g(N / 64, M / 64, BH), blk(256);
    if (tb) gemm_k<true ><<<g, blk>>>(A, aso, asi, lda, B, bso, bsi, ldb, C, cso, csi, ldc, E, eso, esi, lde, K, alpha, beta);
    else    gemm_k<false><<<g, blk>>>(A, aso, asi, lda, B, bso, bsi, ldb, C, cso, csi, ldc, E, eso, esi, lde, K, alpha, beta);
}

extern "C" void kernel_launch(void* const* d_in, const int* in_sizes, int n_in,
                              void* d_out, int out_size)
{
    const float* q  = (const float*)d_in[0];
    const float* k  = (const float*)d_in[1];
    const float* v  = (const float*)d_in[2];
    const float* rw = (const float*)d_in[3];
    float* out = (float*)d_out;

    float *QL, *KL, *X, *ZA, *ZB, *XZ, *T2, *T3, *S, *G, *W, *OA;
    cudaGetSymbolAddress((void**)&QL, g_QL);
    cudaGetSymbolAddress((void**)&KL, g_KL);
    cudaGetSymbolAddress((void**)&X,  g_X);
    cudaGetSymbolAddress((void**)&ZA, g_ZA);
    cudaGetSymbolAddress((void**)&ZB, g_ZB);
    cudaGetSymbolAddress((void**)&XZ, g_XZ);
    cudaGetSymbolAddress((void**)&T2, g_T2);
    cudaGetSymbolAddress((void**)&T3, g_T3);
    cudaGetSymbolAddress((void**)&S,  g_S);
    cudaGetSymbolAddress((void**)&G,  g_G);
    cudaGetSymbolAddress((void**)&W,  g_W);
    cudaGetSymbolAddress((void**)&OA, g_OA);

    const size_t LB = (size_t)MM * DD;       // landmark per-bh: 16384
    const size_t XB = (size_t)MM * MM;       // 65536
    const size_t SB = (size_t)NN_ * MM;      // 1048576
    const size_t OB = (size_t)NN_ * DD;      // 262144
    const size_t QSO = (size_t)NN_ * HH * DD;// raw tensor per-b stride: 2097152
    const size_t QSI = DD;                   // raw tensor per-h stride: 64
    const int    QLD = HH * DD;              // raw tensor row stride: 512

    // 1) landmarks (q pre-scaled)
    landmarks_k<<<dim3(MM, BH), DD>>>(q, k);

    // 2) attn2 scores: X = QL @ KL^T  (256x256, K=64)
    gemm(true, QL, 8*LB, LB, DD,  KL, 8*LB, LB, DD,  X, 8*XB, XB, MM,
         nullptr, 0, 0, 0,  MM, MM, DD, 1.0f, 0.0f);
    // 3) softmax rows
    softmax_rows_k<<<BH * MM, 256>>>(X, MM);

    // 4-6) pinv init: z0 = X^T / (max colsum * max rowsum)
    zero_scal_k<<<1, 32>>>();
    colrow_max_k<<<BH, 256>>>(X);
    z0_k<<<dim3(MM/32, MM/32, BH), dim3(32, 32)>>>(X, ZA);

    // 7) Newton-Schulz iterations: z = 0.25 z (13I - xz(15I - xz(7I - xz)))
    for (int it = 0; it < 6; it++) {
        float* zc = (it & 1) ? ZB : ZA;
        float* zn = (it & 1) ? ZA : ZB;
        // XZ = X @ zc
        gemm(false, X, 8*XB, XB, MM,  zc, 8*XB, XB, MM,  XZ, 8*XB, XB, MM,
             nullptr, 0, 0, 0,  MM, MM, MM, 1.0f, 0.0f);
        // T2 = 7*XZ - XZ@XZ
        gemm(false, XZ, 8*XB, XB, MM,  XZ, 8*XB, XB, MM,  T2, 8*XB, XB, MM,
             XZ, 8*XB, XB, MM,  MM, MM, MM, -1.0f, 7.0f);
        // T3 = 15*XZ - XZ@T2
        gemm(false, XZ, 8*XB, XB, MM,  T2, 8*XB, XB, MM,  T3, 8*XB, XB, MM,
             XZ, 8*XB, XB, MM,  MM, MM, MM, -1.0f, 15.0f);
        // zn = 3.25*zc - 0.25*zc@T3
        gemm(false, zc, 8*XB, XB, MM,  T3, 8*XB, XB, MM,  zn, 8*XB, XB, MM,
             zc, 8*XB, XB, MM,  MM, MM, MM, -0.25f, 3.25f);
    }
    // after 6 iters final z is in ZA

    // 8) attn3 scores: S = QL @ k^T  (256x4096, K=64), k addressed in-place
    gemm(true, QL, 8*LB, LB, DD,  k, QSO, QSI, QLD,  S, 8*SB, SB, NN_,
         nullptr, 0, 0, 0,  MM, NN_, DD, 1.0f, 0.0f);
    // 9) softmax rows (256 rows x 4096 per bh)
    softmax_rows_k<<<BH * MM, 256>>>(S, NN_);
    // 10) G = S @ v  (256x64, K=4096)
    gemm(false, S, 8*SB, SB, NN_,  v, QSO, QSI, QLD,  G, 8*LB, LB, DD,
         nullptr, 0, 0, 0,  MM, DD, NN_, 1.0f, 0.0f);
    // 11) W = ZA @ G  (256x64, K=256)
    gemm(false, ZA, 8*XB, XB, MM,  G, 8*LB, LB, DD,  W, 8*LB, LB, DD,
         nullptr, 0, 0, 0,  MM, DD, MM, 1.0f, 0.0f);

    // 12) attn1 scores: S = scale * q @ KL^T  (4096x256, K=64)
    gemm(true, q, QSO, QSI, QLD,  KL, 8*LB, LB, DD,  S, 8*SB, SB, MM,
         nullptr, 0, 0, 0,  NN_, MM, DD, 0.125f, 0.0f);
    // 13) softmax rows (4096 rows x 256 per bh)
    softmax_rows_k<<<BH * NN_, 256>>>(S, MM);
    // 14) OA = S @ W  (4096x64, K=256)
    gemm(false, S, 8*SB, SB, MM,  W, 8*LB, LB, DD,  OA, 8*OB, OB, DD,
         nullptr, 0, 0, 0,  NN_, DD, MM, 1.0f, 0.0f);

    // 15) depthwise conv residual + add + transpose to (b,n,h,d)
    epilogue_k<<<dim3(NN_, BB), HH * DD>>>(v, rw, OA, out);
}

// round 4
// speedup vs baseline: 1.7408x; 1.7408x over previous
#include <cuda_runtime.h>
#include <cstdint>
#include <cstddef>

#define BB   4
#define NN_  4096
#define HH   8
#define DD   64
#define MM   256
#define LL   16
#define BH   32
#define KERN 33
#define GSPLIT 8

#if defined(__CUDA_ARCH_FEAT_SM103_ALL) || defined(__CUDA_ARCH_FEAT_SM100_ALL)
#define HAS_TC 1
#else
#define HAS_TC 0
#endif

// ---------------- scratch -----------------------------------------------------
__device__ float g_QL[BH * MM * DD];
__device__ float g_KL[BH * MM * DD];
__device__ float g_X [BH * MM * MM];
__device__ float g_ZA[BH * MM * MM];
__device__ float g_ZB[BH * MM * MM];
__device__ float g_XZ[BH * MM * MM];
__device__ float g_T2[BH * MM * MM];
__device__ float g_T3[BH * MM * MM];
__device__ float g_S [BH * (size_t)NN_ * MM];
__device__ float g_G [BH * MM * DD];
__device__ float g_Gp[GSPLIT * BH * MM * DD];
__device__ float g_W [BH * MM * DD];
__device__ float g_OA[BH * (size_t)NN_ * DD];
__device__ float g_scal[2];

// ---------------- PTX helpers -------------------------------------------------
__device__ __forceinline__ uint32_t elect_one_pred() {
    uint32_t pred;
    asm volatile("{\n\t.reg .pred p;\n\telect.sync _|p, 0xFFFFFFFF;\n\tselp.b32 %0, 1, 0, p;\n\t}"
                 : "=r"(pred));
    return pred;
}
__device__ __forceinline__ uint32_t smem_to_u32(const void* p) {
    uint32_t a;
    asm("{ .reg .u64 t; cvta.to.shared.u64 t, %1; cvt.u32.u64 %0, t; }" : "=r"(a) : "l"(p));
    return a;
}
#define SMEM_SWIZZLE_128B(o) ((o) ^ (((o) >> 3) & 0x70))

static constexpr uint64_t SMEM_DESC_BASE_SW128 =
    (uint64_t(2) << 61) | (uint64_t(1) << 46) | (uint64_t(64) << 32) | (uint64_t(1) << 16);
#define MAKE_SMEM_DESC(base_addr) (SMEM_DESC_BASE_SW128 | ((uint64_t)((base_addr) >> 4) & 0x3FFF))

#define FENCE_PROXY_ASYNC_SHARED_CTA() \
    asm volatile("fence.proxy.async.shared::cta;" ::: "memory")
#define MBARRIER_INIT(a, c) \
    asm volatile("mbarrier.init.shared.b64 [%0], %1;" :: "r"((uint32_t)(a)), "r"((uint32_t)(c)) : "memory")
#define MBARRIER_INVAL(a) \
    asm volatile("mbarrier.inval.shared.b64 [%0];" :: "r"((uint32_t)(a)) : "memory")
#define MBARRIER_WAIT_PARITY(mbar_smem_addr, phase_parity) do { \
    uint32_t _mbar = (uint32_t)(mbar_smem_addr); \
    uint32_t _parity = (uint32_t)(phase_parity); \
    uint32_t _done; \
    asm volatile("{\n\t.reg .pred p;\n\t" \
        "mbarrier.try_wait.parity.acquire.cta.shared::cta.b64 p, [%1], %2;\n\t" \
        "selp.b32 %0, 1, 0, p;\n\t}" \
        : "=r"(_done) : "r"(_mbar), "r"(_parity) : "memory"); \
    if (!_done) { \
        asm volatile("{\n\t.reg .pred P1;\n\t" \
            "WAIT_LOOP_%=:\n\t" \
            "mbarrier.try_wait.parity.acquire.cta.shared::cta.b64 P1, [%0], %1, 0x989680;\n\t" \
            "@P1 bra.uni WAIT_DONE_%=;\n\t" \
            "bra.uni WAIT_LOOP_%=;\n\t" \
            "WAIT_DONE_%=:\n\t}" \
            :: "r"(_mbar), "r"(_parity) : "memory"); \
    } \
} while(0)

#if HAS_TC
#define TCGEN05_ALLOC(smem_result_addr, nCols) \
    asm volatile("tcgen05.alloc.cta_group::1.sync.aligned.shared::cta.b32 [%0], %1;" \
                 :: "r"((uint32_t)(smem_result_addr)), "r"((uint32_t)(nCols)) : "memory")
#define TCGEN05_DEALLOC(tmem_addr, nCols) \
    asm volatile("tcgen05.dealloc.cta_group::1.sync.aligned.b32 %0, %1;" \
                 :: "r"(tmem_addr), "r"((uint32_t)(nCols)))
#define TCGEN05_RELINQUISH_ALLOC_PERMIT() \
    asm volatile("tcgen05.relinquish_alloc_permit.cta_group::1.sync.aligned;")
#define TCGEN05_COMMIT(mbar_smem_addr) \
    asm volatile("tcgen05.commit.cta_group::1.mbarrier::arrive::one.shared::cluster.b64 [%0];" \
                 :: "r"((uint32_t)(mbar_smem_addr)) : "memory")
#define TCGEN05_FENCE_AFTER() \
    asm volatile("tcgen05.fence::after_thread_sync;" ::: "memory")
#define TCGEN05_WAIT_LD() \
    asm volatile("tcgen05.wait::ld.sync.aligned;" ::: "memory")
#define TCGEN05_LD_32X32B_X32(r, tmem_addr) \
    asm volatile("tcgen05.ld.sync.aligned.32x32b.x32.b32 " \
        "{%0, %1, %2, %3, %4, %5, %6, %7, %8, %9, %10, %11, %12, %13, %14, %15, " \
        " %16, %17, %18, %19, %20, %21, %22, %23, %24, %25, %26, %27, %28, %29, %30, %31}, [%32];" \
        : "=r"((r)[0]),  "=r"((r)[1]),  "=r"((r)[2]),  "=r"((r)[3]), \
          "=r"((r)[4]),  "=r"((r)[5]),  "=r"((r)[6]),  "=r"((r)[7]), \
          "=r"((r)[8]),  "=r"((r)[9]),  "=r"((r)[10]), "=r"((r)[11]), \
          "=r"((r)[12]), "=r"((r)[13]), "=r"((r)[14]), "=r"((r)[15]), \
          "=r"((r)[16]), "=r"((r)[17]), "=r"((r)[18]), "=r"((r)[19]), \
          "=r"((r)[20]), "=r"((r)[21]), "=r"((r)[22]), "=r"((r)[23]), \
          "=r"((r)[24]), "=r"((r)[25]), "=r"((r)[26]), "=r"((r)[27]), \
          "=r"((r)[28]), "=r"((r)[29]), "=r"((r)[30]), "=r"((r)[31]) \
        : "r"(tmem_addr))

__device__ __forceinline__ void mma_tf32_ss(uint32_t d, uint64_t a, uint64_t b,
                                            uint32_t idesc, uint32_t en) {
    asm volatile("{\n\t.reg .pred p;\n\tsetp.ne.u32 p, %4, 0;\n\t"
                 "tcgen05.mma.cta_group::1.kind::tf32 [%0], %1, %2, %3, p;\n\t}"
                 :: "r"(d), "l"(a), "l"(b), "r"(idesc), "r"(en) : "memory");
}
#endif // HAS_TC

// ---------------- landmarks ---------------------------------------------------
__global__ void landmarks_k(const float* __restrict__ q, const float* __restrict__ k)
{
    int bh = blockIdx.y, i = blockIdx.x, d = threadIdx.x;
    int b = bh >> 3, h = bh & 7;
    float sq = 0.f, sk = 0.f;
    #pragma unroll
    for (int j = 0; j < LL; j++) {
        size_t idx = (((size_t)b * NN_ + (size_t)i * LL + j) * HH + h) * DD + d;
        sq += q[idx];
        sk += k[idx];
    }
    size_t o = ((size_t)bh * MM + i) * DD + d;
    g_QL[o] = sq * (0.125f / (float)LL);
    g_KL[o] = sk * (1.0f  / (float)LL);
}

// ---------------- tcgen05 tf32 batched GEMM ----------------------------------
// C = alpha * (A @ B^T) + beta * E.
// A: [M,K] row-major ld=lda. B: logical [N,K];
//   TRANSB=false: stored [N,K] row-major ld=ldb (direct copy into SMEM).
//   TRANSB=true : stored [K,N] row-major ld=ldb (transposed during STS).
// Batch: z -> (bh, split); operand offset = b*so + h*si. K-split writes partials
// at C + s*c_split.
template<int NT, bool TRANSB>
__global__ void __launch_bounds__(128)
tcgemm_k(const float* __restrict__ A, size_t a_so, size_t a_si, int lda,
         const float* __restrict__ B, size_t b_so, size_t b_si, int ldb,
         float* __restrict__ C, size_t c_so, size_t c_si, int ldc,
         const float* __restrict__ E, size_t e_so, size_t e_si, int lde,
         int K, int nsplit, size_t c_split, float alpha, float beta)
{
#if HAS_TC
    extern __shared__ char dsm[];
    uint32_t base  = smem_to_u32(dsm);
    uint32_t abase = (base + 1023u) & ~1023u;
    uint32_t bbase = abase + 128 * 128;          // A tile: 128 rows x 128B
    uint32_t aux   = bbase + NT * 128;           // B tile: NT rows x 128B
    char* dA = dsm + (abase - base);
    char* dB = dsm + (bbase - base);
    uint32_t tptr_addr = aux;
    uint32_t mbar_addr = aux + 8;

    int t = threadIdx.x, wid = t >> 5, lid = t & 31;
    int z = blockIdx.z, bh = z / nsplit, s = z - bh * nsplit;
    int b = bh >> 3, h = bh & 7;
    A += (size_t)b * a_so + (size_t)h * a_si;
    B += (size_t)b * b_so + (size_t)h * b_si;
    C += (size_t)b * c_so + (size_t)h * c_si + (size_t)s * c_split;
    if (E) E += (size_t)b * e_so + (size_t)h * e_si;

    const int m0 = blockIdx.y * 128;
    const int n0 = blockIdx.x * NT;
    const int Kper = K / nsplit;
    const int kb0 = s * Kper;
    const int nchunk = Kper >> 5;

    if (wid == 0) TCGEN05_ALLOC(tptr_addr, NT);
    if (t == 0) MBARRIER_INIT(mbar_addr, 1);
    __syncthreads();
    uint32_t tmem;
    asm volatile("ld.shared.b32 %0, [%1];" : "=r"(tmem) : "r"(tptr_addr));
    if (wid == 0) TCGEN05_RELINQUISH_ALLOC_PERMIT();

    const uint32_t idesc = (1u << 4) | (2u << 7) | (2u << 10) |
                           ((uint32_t)(NT / 8) << 17) | (8u << 24);
    const uint64_t adesc0 = MAKE_SMEM_DESC(abase);
    const uint64_t bdesc0 = MAKE_SMEM_DESC(bbase);

    for (int c = 0; c < nchunk; c++) {
        const int kb = kb0 + c * 32;
        // A chunk: 128 rows x 32 floats, SW128
        #pragma unroll
        for (int p = 0; p < 8; p++) {
            int idx = t + p * 128;
            int r = idx >> 3, f = idx & 7;
            float4 v4 = *(const float4*)(A + (size_t)(m0 + r) * lda + kb + f * 4);
            uint32_t off = (uint32_t)(r * 128 + f * 16);
            *(float4*)(dA + SMEM_SWIZZLE_128B(off)) = v4;
        }
        // B chunk: NT rows x 32 floats
        if (!TRANSB) {
            #pragma unroll
            for (int p = 0; p < NT / 16; p++) {
                int idx = t + p * 128;
                int r = idx >> 3, f = idx & 7;
                float4 v4 = *(const float4*)(B + (size_t)(n0 + r) * ldb + kb + f * 4);
                uint32_t off = (uint32_t)(r * 128 + f * 16);
                *(float4*)(dB + SMEM_SWIZZLE_128B(off)) = v4;
            }
        } else {
            constexpr int NF = NT / 4;
            #pragma unroll
            for (int p = 0; p < (32 * NF) / 128; p++) {
                int idx = t + p * 128;
                int kk = idx / NF, nf = idx - kk * NF;
                float4 v4 = *(const float4*)(B + (size_t)(kb + kk) * ldb + n0 + nf * 4);
                int nb = nf * 4;
                *(float*)(dB + SMEM_SWIZZLE_128B((uint32_t)((nb + 0) * 128 + kk * 4))) = v4.x;
                *(float*)(dB + SMEM_SWIZZLE_128B((uint32_t)((nb + 1) * 128 + kk * 4))) = v4.y;
                *(float*)(dB + SMEM_SWIZZLE_128B((uint32_t)((nb + 2) * 128 + kk * 4))) = v4.z;
                *(float*)(dB + SMEM_SWIZZLE_128B((uint32_t)((nb + 3) * 128 + kk * 4))) = v4.w;
            }
        }
        FENCE_PROXY_ASYNC_SHARED_CTA();
        __syncthreads();
        if (wid == 0) {
            if (elect_one_pred()) {
                #pragma unroll
                for (int st = 0; st < 4; st++) {   // 4 x K=8 covers Kc=32 (32B -> +2 desc units)
                    mma_tf32_ss(tmem, adesc0 + st * 2, bdesc0 + st * 2, idesc,
                                (c > 0 || st > 0) ? 1u : 0u);
                }
                TCGEN05_COMMIT(mbar_addr);
            }
        }
        MBARRIER_WAIT_PARITY(mbar_addr, c & 1);
    }

    TCGEN05_FENCE_AFTER();
    // Epilogue: warp w owns D rows [32w, 32w+32)
    const int m = m0 + wid * 32 + lid;
    #pragma unroll
    for (int cb = 0; cb < NT; cb += 32) {
        uint32_t r[32];
        TCGEN05_LD_32X32B_X32(r, tmem + cb);
        TCGEN05_WAIT_LD();
        float* crow = C + (size_t)m * ldc + (n0 + cb);
        const float* erow = E ? (E + (size_t)m * lde + (n0 + cb)) : (const float*)0;
        #pragma unroll
        for (int j = 0; j < 32; j += 4) {
            float4 o;
            o.x = alpha * __uint_as_float(r[j + 0]);
            o.y = alpha * __uint_as_float(r[j + 1]);
            o.z = alpha * __uint_as_float(r[j + 2]);
            o.w = alpha * __uint_as_float(r[j + 3]);
            if (erow) {
                float4 e4 = *(const float4*)(erow + j);
                o.x += beta * e4.x; o.y += beta * e4.y;
                o.z += beta * e4.z; o.w += beta * e4.w;
            }
            *(float4*)(crow + j) = o;
        }
    }
    __syncthreads();
    if (t == 0) MBARRIER_INVAL(mbar_addr);
    __syncthreads();
    if (wid == 0) TCGEN05_DEALLOC(tmem, NT);
#else
    // Non-sm_103a PTX fallback pass: never executed (harness runs the
    // sm_103a cubin); present only so the generic compute_103 PTX assembles.
    __trap();
#endif
}

// ---------------- register-resident row softmax ------------------------------
template<int C>
__global__ void softmax_reg_k(float* __restrict__ X)
{
    constexpr int V = C / 256;
    float* row = X + (size_t)blockIdx.x * C;
    int t = threadIdx.x;
    float v[V];
    float mx = -1e30f;
    #pragma unroll
    for (int i = 0; i < V; i++) { v[i] = row[t + i * 256]; mx = fmaxf(mx, v[i]); }
    __shared__ float red[256];
    red[t] = mx; __syncthreads();
    for (int s = 128; s > 0; s >>= 1) { if (t < s) red[t] = fmaxf(red[t], red[t + s]); __syncthreads(); }
    mx = red[0]; __syncthreads();
    float sum = 0.f;
    #pragma unroll
    for (int i = 0; i < V; i++) { v[i] = __expf(v[i] - mx); sum += v[i]; }
    red[t] = sum; __syncthreads();
    for (int s = 128; s > 0; s >>= 1) { if (t < s) red[t] += red[t + s]; __syncthreads(); }
    float inv = 1.0f / red[0];
    #pragma unroll
    for (int i = 0; i < V; i++) row[t + i * 256] = v[i] * inv;
}

// ---------------- pinv init ---------------------------------------------------
__global__ void zero_scal_k() { if (threadIdx.x < 2) g_scal[threadIdx.x] = 0.f; }

__global__ void colrow_max_k(const float* __restrict__ X)
{
    int bh = blockIdx.x, t = threadIdx.x;
    const float* xb = X + (size_t)bh * MM * MM;
    float cs = 0.f, rs = 0.f;
    for (int i = 0; i < MM; i++) cs += xb[(size_t)i * MM + t];
    for (int j = 0; j < MM; j++) rs += xb[(size_t)t * MM + j];
    __shared__ float rc[256], rr[256];
    rc[t] = cs; rr[t] = rs; __syncthreads();
    for (int s = 128; s > 0; s >>= 1) {
        if (t < s) { rc[t] = fmaxf(rc[t], rc[t + s]); rr[t] = fmaxf(rr[t], rr[t + s]); }
        __syncthreads();
    }
    if (t == 0) {
        atomicMax((int*)&g_scal[0], __float_as_int(rc[0]));
        atomicMax((int*)&g_scal[1], __float_as_int(rr[0]));
    }
}

__global__ void z0_k(const float* __restrict__ X, float* __restrict__ Z)
{
    __shared__ float tile[32][33];
    int bh = blockIdx.z;
    const float* xb = X + (size_t)bh * MM * MM;
    float* zb = Z + (size_t)bh * MM * MM;
    int i0 = blockIdx.x * 32, j0 = blockIdx.y * 32;
    tile[threadIdx.y][threadIdx.x] = xb[(size_t)(j0 + threadIdx.y) * MM + (i0 + threadIdx.x)];
    __syncthreads();
    float inv = 1.0f / (g_scal[0] * g_scal[1]);
    zb[(size_t)(i0 + threadIdx.y) * MM + (j0 + threadIdx.x)] = tile[threadIdx.x][threadIdx.y] * inv;
}

// ---------------- K-split reduce for G ---------------------------------------
__global__ void reduce_g_k(const float* __restrict__ Gp, float* __restrict__ G)
{
    int i = blockIdx.x * 256 + threadIdx.x;
    const size_t stride = (size_t)BH * MM * DD;
    float s = 0.f;
    #pragma unroll
    for (int p = 0; p < GSPLIT; p++) s += Gp[(size_t)p * stride + i];
    G[i] = s;
}

// ---------------- epilogue: depthwise conv + residual + transpose ------------
__global__ void epilogue_k(const float* __restrict__ v, const float* __restrict__ rw,
                           const float* __restrict__ OA, float* __restrict__ out)
{
    __shared__ float vt[96 * 64];
    __shared__ float w[KERN];
    int bh = blockIdx.y, b = bh >> 3, h = bh & 7;
    int i0 = blockIdx.x * 64;
    int t = threadIdx.x;
    if (t < KERN) w[t] = rw[h * KERN + t];
    #pragma unroll
    for (int p = 0; p < 6; p++) {
        int idx = t + p * 256;
        int r = idx >> 4, f = idx & 15;
        int ii = i0 - 16 + r;
        float4 val = make_float4(0.f, 0.f, 0.f, 0.f);
        if (ii >= 0 && ii < NN_)
            val = *(const float4*)(v + (((size_t)b * NN_ + ii) * HH + h) * DD + f * 4);
        *(float4*)(vt + r * 64 + f * 4) = val;
    }
    __syncthreads();
    int d4 = (t & 15) * 4;
    int irow = t >> 4;
    #pragma unroll
    for (int rr = 0; rr < 4; rr++) {
        int il = irow + rr * 16;
        int i = i0 + il;
        float4 acc = *(const float4*)(OA + ((size_t)bh * NN_ + i) * DD + d4);
        #pragma unroll
        for (int tap = 0; tap < KERN; tap++) {
            float4 vv = *(const float4*)(vt + (il + tap) * 64 + d4);
            float wt = w[tap];
            acc.x += vv.x * wt; acc.y += vv.y * wt;
            acc.z += vv.z * wt; acc.w += vv.w * wt;
        }
        *(float4*)(out + (((size_t)b * NN_ + i) * HH + h) * DD + d4) = acc;
    }
}

// ---------------- host side ---------------------------------------------------
static void tcg(bool transb, int NT,
                const float* A, size_t aso, size_t asi, int lda,
                const float* B, size_t bso, size_t bsi, int ldb,
                float* C, size_t cso, size_t csi, int ldc,
                const float* E, size_t eso, size_t esi, int lde,
                int M, int N, int K, int nsplit, size_t csplit,
                float alpha, float beta)
{
    dim3 g(N / NT, M / 128, BH * nsplit);
    size_t shm = 1024 + 128 * 128 + (size_t)NT * 128 + 64;
    if (NT == 128) {
        if (transb) tcgemm_k<128, true ><<<g, 128, shm>>>(A, aso, asi, lda, B, bso, bsi, ldb, C, cso, csi, ldc, E, eso, esi, lde, K, nsplit, csplit, alpha, beta);
        else        tcgemm_k<128, false><<<g, 128, shm>>>(A, aso, asi, lda, B, bso, bsi, ldb, C, cso, csi, ldc, E, eso, esi, lde, K, nsplit, csplit, alpha, beta);
    } else {
        if (transb) tcgemm_k<64, true ><<<g, 128, shm>>>(A, aso, asi, lda, B, bso, bsi, ldb, C, cso, csi, ldc, E, eso, esi, lde, K, nsplit, csplit, alpha, beta);
        else        tcgemm_k<64, false><<<g, 128, shm>>>(A, aso, asi, lda, B, bso, bsi, ldb, C, cso, csi, ldc, E, eso, esi, lde, K, nsplit, csplit, alpha, beta);
    }
}

extern "C" void kernel_launch(void* const* d_in, const int* in_sizes, int n_in,
                              void* d_out, int out_size)
{
    const float* q  = (const float*)d_in[0];
    const float* k  = (const float*)d_in[1];
    const float* v  = (const float*)d_in[2];
    const float* rw = (const float*)d_in[3];
    float* out = (float*)d_out;

    float *QL, *KL, *X, *ZA, *ZB, *XZ, *T2, *T3, *S, *G, *Gp, *W, *OA;
    cudaGetSymbolAddress((void**)&QL, g_QL);
    cudaGetSymbolAddress((void**)&KL, g_KL);
    cudaGetSymbolAddress((void**)&X,  g_X);
    cudaGetSymbolAddress((void**)&ZA, g_ZA);
    cudaGetSymbolAddress((void**)&ZB, g_ZB);
    cudaGetSymbolAddress((void**)&XZ, g_XZ);
    cudaGetSymbolAddress((void**)&T2, g_T2);
    cudaGetSymbolAddress((void**)&T3, g_T3);
    cudaGetSymbolAddress((void**)&S,  g_S);
    cudaGetSymbolAddress((void**)&G,  g_G);
    cudaGetSymbolAddress((void**)&Gp, g_Gp);
    cudaGetSymbolAddress((void**)&W,  g_W);
    cudaGetSymbolAddress((void**)&OA, g_OA);

    const size_t LB  = (size_t)MM * DD;
    const size_t XB  = (size_t)MM * MM;
    const size_t SB  = (size_t)NN_ * MM;
    const size_t OB  = (size_t)NN_ * DD;
    const size_t QSO = (size_t)NN_ * HH * DD;   // per-b stride of raw tensors
    const size_t QSI = DD;                      // per-h stride of raw tensors
    const int    QLD = HH * DD;                 // row stride of raw tensors

    // 1) landmarks (q landmark pre-scaled by d^-0.5)
    landmarks_k<<<dim3(MM, BH), DD>>>(q, k);

    // 2) attn2 scores: X = QL @ KL^T   [256 x 256, K=64]
    tcg(false, 128, QL, 8*LB, LB, DD,  KL, 8*LB, LB, DD,  X, 8*XB, XB, MM,
        nullptr, 0, 0, 0,  MM, MM, DD, 1, 0, 1.0f, 0.0f);
    softmax_reg_k<MM><<<BH * MM, 256>>>(X);

    // 3) pinv init
    zero_scal_k<<<1, 32>>>();
    colrow_max_k<<<BH, 256>>>(X);
    z0_k<<<dim3(MM/32, MM/32, BH), dim3(32, 32)>>>(X, ZA);

    // 4) Newton-Schulz: z = 0.25 z (13I - xz(15I - xz(7I - xz)))
    for (int it = 0; it < 6; it++) {
        float* zc = (it & 1) ? ZB : ZA;
        float* zn = (it & 1) ? ZA : ZB;
        tcg(true, 128, X,  8*XB, XB, MM,  zc, 8*XB, XB, MM,  XZ, 8*XB, XB, MM,
            nullptr, 0, 0, 0,  MM, MM, MM, 1, 0, 1.0f, 0.0f);
        tcg(true, 128, XZ, 8*XB, XB, MM,  XZ, 8*XB, XB, MM,  T2, 8*XB, XB, MM,
            XZ, 8*XB, XB, MM,  MM, MM, MM, 1, 0, -1.0f, 7.0f);
        tcg(true, 128, XZ, 8*XB, XB, MM,  T2, 8*XB, XB, MM,  T3, 8*XB, XB, MM,
            XZ, 8*XB, XB, MM,  MM, MM, MM, 1, 0, -1.0f, 15.0f);
        tcg(true, 128, zc, 8*XB, XB, MM,  T3, 8*XB, XB, MM,  zn, 8*XB, XB, MM,
            zc, 8*XB, XB, MM,  MM, MM, MM, 1, 0, -0.25f, 3.25f);
    }
    // final z in ZA

    // 5) attn3 scores: S[256,4096] = QL @ k^T (k rows are [N,K] directly)
    tcg(false, 128, QL, 8*LB, LB, DD,  k, QSO, QSI, QLD,  S, 8*SB, SB, NN_,
        nullptr, 0, 0, 0,  MM, NN_, DD, 1, 0, 1.0f, 0.0f);
    softmax_reg_k<NN_><<<BH * MM, 256>>>(S);

    // 6) G = S @ v  [256 x 64, K=4096], K-split x8 + reduce
    tcg(true, 64, S, 8*SB, SB, NN_,  v, QSO, QSI, QLD,  Gp, 8*LB, LB, DD,
        nullptr, 0, 0, 0,  MM, DD, NN_, GSPLIT, (size_t)BH * LB, 1.0f, 0.0f);
    reduce_g_k<<<(BH * MM * DD) / 256, 256>>>(Gp, G);

    // 7) W = ZA @ G  [256 x 64, K=256]
    tcg(true, 64, ZA, 8*XB, XB, MM,  G, 8*LB, LB, DD,  W, 8*LB, LB, DD,
        nullptr, 0, 0, 0,  MM, DD, MM, 1, 0, 1.0f, 0.0f);

    // 8) attn1 scores: S[4096,256] = 0.125 * q @ KL^T
    tcg(false, 128, q, QSO, QSI, QLD,  KL, 8*LB, LB, DD,  S, 8*SB, SB, MM,
        nullptr, 0, 0, 0,  NN_, MM, DD, 1, 0, 0.125f, 0.0f);
    softmax_reg_k<MM><<<BH * NN_, 256>>>(S);

    // 9) OA = S @ W  [4096 x 64, K=256]
    tcg(true, 64, S, 8*SB, SB, MM,  W, 8*LB, LB, DD,  OA, 8*OB, OB, DD,
        nullptr, 0, 0, 0,  NN_, DD, MM, 1, 0, 1.0f, 0.0f);

    // 10) depthwise conv residual + transpose
    epilogue_k<<<dim3(NN_ / 64, BH), 256>>>(v, rw, OA, out);
}

// round 6
// speedup vs baseline: 2.4410x; 1.4023x over previous
#include <cuda_runtime.h>
#include <cstdint>
#include <cstddef>

#define BB   4
#define NN_  4096
#define HH   8
#define DD   64
#define MM   256
#define LL   16
#define BH   32
#define KERN 33
#define GSPLIT 8

#if defined(__CUDA_ARCH_FEAT_SM103_ALL) || defined(__CUDA_ARCH_FEAT_SM100_ALL)
#define HAS_TC 1
#else
#define HAS_TC 0
#endif

// ---------------- scratch -----------------------------------------------------
__device__ float g_QL[BH * MM * DD];
__device__ float g_KL[BH * MM * DD];
__device__ float g_X [BH * MM * MM];
__device__ float g_ZA[BH * MM * MM];
__device__ float g_ZB[BH * MM * MM];
__device__ float g_XZ[BH * MM * MM];
__device__ float g_T2[BH * MM * MM];
__device__ float g_T3[BH * MM * MM];
__device__ float g_S [BH * (size_t)NN_ * MM];
__device__ float g_G [BH * MM * DD];
__device__ float g_Gp[GSPLIT * BH * MM * DD];
__device__ float g_W [BH * MM * DD];
__device__ float g_OA[BH * (size_t)NN_ * DD];
__device__ float g_scal[2];

// ---------------- PTX helpers -------------------------------------------------
__device__ __forceinline__ uint32_t elect_one_pred() {
    uint32_t pred;
    asm volatile("{\n\t.reg .pred p;\n\telect.sync _|p, 0xFFFFFFFF;\n\tselp.b32 %0, 1, 0, p;\n\t}"
                 : "=r"(pred));
    return pred;
}
__device__ __forceinline__ uint32_t smem_to_u32(const void* p) {
    uint32_t a;
    asm("{ .reg .u64 t; cvta.to.shared.u64 t, %1; cvt.u32.u64 %0, t; }" : "=r"(a) : "l"(p));
    return a;
}
#define SMEM_SWIZZLE_128B(o) ((o) ^ (((o) >> 3) & 0x70))

static constexpr uint64_t SMEM_DESC_BASE_SW128 =
    (uint64_t(2) << 61) | (uint64_t(1) << 46) | (uint64_t(64) << 32) | (uint64_t(1) << 16);
#define MAKE_SMEM_DESC(base_addr) (SMEM_DESC_BASE_SW128 | ((uint64_t)((base_addr) >> 4) & 0x3FFF))

#define FENCE_PROXY_ASYNC_SHARED_CTA() \
    asm volatile("fence.proxy.async.shared::cta;" ::: "memory")
#define MBARRIER_INIT(a, c) \
    asm volatile("mbarrier.init.shared.b64 [%0], %1;" :: "r"((uint32_t)(a)), "r"((uint32_t)(c)) : "memory")
#define MBARRIER_INVAL(a) \
    asm volatile("mbarrier.inval.shared.b64 [%0];" :: "r"((uint32_t)(a)) : "memory")
#define MBARRIER_WAIT_PARITY(mbar_smem_addr, phase_parity) do { \
    uint32_t _mbar = (uint32_t)(mbar_smem_addr); \
    uint32_t _parity = (uint32_t)(phase_parity); \
    uint32_t _done; \
    asm volatile("{\n\t.reg .pred p;\n\t" \
        "mbarrier.try_wait.parity.acquire.cta.shared::cta.b64 p, [%1], %2;\n\t" \
        "selp.b32 %0, 1, 0, p;\n\t}" \
        : "=r"(_done) : "r"(_mbar), "r"(_parity) : "memory"); \
    if (!_done) { \
        asm volatile("{\n\t.reg .pred P1;\n\t" \
            "WAIT_LOOP_%=:\n\t" \
            "mbarrier.try_wait.parity.acquire.cta.shared::cta.b64 P1, [%0], %1, 0x989680;\n\t" \
            "@P1 bra.uni WAIT_DONE_%=;\n\t" \
            "bra.uni WAIT_LOOP_%=;\n\t" \
            "WAIT_DONE_%=:\n\t}" \
            :: "r"(_mbar), "r"(_parity) : "memory"); \
    } \
} while(0)

#if HAS_TC
#define TCGEN05_ALLOC(smem_result_addr, nCols) \
    asm volatile("tcgen05.alloc.cta_group::1.sync.aligned.shared::cta.b32 [%0], %1;" \
                 :: "r"((uint32_t)(smem_result_addr)), "r"((uint32_t)(nCols)) : "memory")
#define TCGEN05_DEALLOC(tmem_addr, nCols) \
    asm volatile("tcgen05.dealloc.cta_group::1.sync.aligned.b32 %0, %1;" \
                 :: "r"(tmem_addr), "r"((uint32_t)(nCols)))
#define TCGEN05_RELINQUISH_ALLOC_PERMIT() \
    asm volatile("tcgen05.relinquish_alloc_permit.cta_group::1.sync.aligned;")
#define TCGEN05_COMMIT(mbar_smem_addr) \
    asm volatile("tcgen05.commit.cta_group::1.mbarrier::arrive::one.shared::cluster.b64 [%0];" \
                 :: "r"((uint32_t)(mbar_smem_addr)) : "memory")
#define TCGEN05_FENCE_AFTER() \
    asm volatile("tcgen05.fence::after_thread_sync;" ::: "memory")
#define TCGEN05_WAIT_LD() \
    asm volatile("tcgen05.wait::ld.sync.aligned;" ::: "memory")
#define TCGEN05_LD_32X32B_X32(r, tmem_addr) \
    asm volatile("tcgen05.ld.sync.aligned.32x32b.x32.b32 " \
        "{%0, %1, %2, %3, %4, %5, %6, %7, %8, %9, %10, %11, %12, %13, %14, %15, " \
        " %16, %17, %18, %19, %20, %21, %22, %23, %24, %25, %26, %27, %28, %29, %30, %31}, [%32];" \
        : "=r"((r)[0]),  "=r"((r)[1]),  "=r"((r)[2]),  "=r"((r)[3]), \
          "=r"((r)[4]),  "=r"((r)[5]),  "=r"((r)[6]),  "=r"((r)[7]), \
          "=r"((r)[8]),  "=r"((r)[9]),  "=r"((r)[10]), "=r"((r)[11]), \
          "=r"((r)[12]), "=r"((r)[13]), "=r"((r)[14]), "=r"((r)[15]), \
          "=r"((r)[16]), "=r"((r)[17]), "=r"((r)[18]), "=r"((r)[19]), \
          "=r"((r)[20]), "=r"((r)[21]), "=r"((r)[22]), "=r"((r)[23]), \
          "=r"((r)[24]), "=r"((r)[25]), "=r"((r)[26]), "=r"((r)[27]), \
          "=r"((r)[28]), "=r"((r)[29]), "=r"((r)[30]), "=r"((r)[31]) \
        : "r"(tmem_addr))

__device__ __forceinline__ void mma_tf32_ss(uint32_t d, uint64_t a, uint64_t b,
                                            uint32_t idesc, uint32_t en) {
    asm volatile("{\n\t.reg .pred p;\n\tsetp.ne.u32 p, %4, 0;\n\t"
                 "tcgen05.mma.cta_group::1.kind::tf32 [%0], %1, %2, %3, p;\n\t}"
                 :: "r"(d), "l"(a), "l"(b), "r"(idesc), "r"(en) : "memory");
}
#endif // HAS_TC

// ---------------- landmarks (also zeroes g_scal) ------------------------------
__global__ void landmarks_k(const float* __restrict__ q, const float* __restrict__ k)
{
    int bh = blockIdx.y, i = blockIdx.x, d = threadIdx.x;
    if (bh == 0 && i == 0 && d < 2) g_scal[d] = 0.f;
    int b = bh >> 3, h = bh & 7;
    float sq = 0.f, sk = 0.f;
    #pragma unroll
    for (int j = 0; j < LL; j++) {
        size_t idx = (((size_t)b * NN_ + (size_t)i * LL + j) * HH + h) * DD + d;
        sq += q[idx];
        sk += k[idx];
    }
    size_t o = ((size_t)bh * MM + i) * DD + d;
    g_QL[o] = sq * (0.125f / (float)LL);
    g_KL[o] = sk * (1.0f  / (float)LL);
}

// ---------------- tcgen05 tf32 batched GEMM (2-stage pipelined) ---------------
// C = alpha * (A @ B^T) + beta * E.   A: [M,K] rm ld=lda.
// TRANSB=false: B stored [N,K] rm; TRANSB=true: B stored [K,N] rm.
template<int NT, bool TRANSB>
__global__ void __launch_bounds__(128)
tcgemm_k(const float* __restrict__ A, size_t a_so, size_t a_si, int lda,
         const float* __restrict__ B, size_t b_so, size_t b_si, int ldb,
         float* __restrict__ C, size_t c_so, size_t c_si, int ldc,
         const float* __restrict__ E, size_t e_so, size_t e_si, int lde,
         int K, int nsplit, size_t c_split, float alpha, float beta)
{
#if HAS_TC
    extern __shared__ char dsm[];
    uint32_t base  = smem_to_u32(dsm);
    uint32_t abase0 = (base + 1023u) & ~1023u;
    uint32_t abase1 = abase0 + 128 * 128;
    uint32_t bbase0 = abase1 + 128 * 128;
    uint32_t bbase1 = bbase0 + NT * 128;
    uint32_t aux    = bbase1 + NT * 128;
    char* dA0 = dsm + (abase0 - base);
    char* dA1 = dsm + (abase1 - base);
    char* dB0 = dsm + (bbase0 - base);
    char* dB1 = dsm + (bbase1 - base);
    uint32_t tptr_addr = aux;
    uint32_t mbar0 = aux + 8;
    uint32_t mbar1 = aux + 16;

    int t = threadIdx.x, wid = t >> 5;
    int z = blockIdx.z, bh = z / nsplit, s = z - bh * nsplit;
    int b = bh >> 3, h = bh & 7;
    A += (size_t)b * a_so + (size_t)h * a_si;
    B += (size_t)b * b_so + (size_t)h * b_si;
    C += (size_t)b * c_so + (size_t)h * c_si + (size_t)s * c_split;
    if (E) E += (size_t)b * e_so + (size_t)h * e_si;

    const int m0 = blockIdx.y * 128;
    const int n0 = blockIdx.x * NT;
    const int Kper = K / nsplit;
    const int kb0 = s * Kper;
    const int nchunk = Kper >> 5;

    if (wid == 0) TCGEN05_ALLOC(tptr_addr, NT);
    if (t == 0) { MBARRIER_INIT(mbar0, 1); MBARRIER_INIT(mbar1, 1); }
    __syncthreads();
    uint32_t tmem;
    asm volatile("ld.shared.b32 %0, [%1];" : "=r"(tmem) : "r"(tptr_addr));
    if (wid == 0) TCGEN05_RELINQUISH_ALLOC_PERMIT();

    const uint32_t idesc = (1u << 4) | (2u << 7) | (2u << 10) |
                           ((uint32_t)(NT / 8) << 17) | (8u << 24);
    const uint64_t adesc[2] = { MAKE_SMEM_DESC(abase0), MAKE_SMEM_DESC(abase1) };
    const uint64_t bdesc[2] = { MAKE_SMEM_DESC(bbase0), MAKE_SMEM_DESC(bbase1) };

    int ph0 = 0, ph1 = 0;
    for (int c = 0; c < nchunk; c++) {
        const int st = c & 1;
        if (c >= 2) {
            if (st) { MBARRIER_WAIT_PARITY(mbar1, ph1); ph1 ^= 1; }
            else    { MBARRIER_WAIT_PARITY(mbar0, ph0); ph0 ^= 1; }
        }
        char* dA = st ? dA1 : dA0;
        char* dB = st ? dB1 : dB0;
        const int kb = kb0 + c * 32;
        #pragma unroll
        for (int p = 0; p < 8; p++) {
            int idx = t + p * 128;
            int r = idx >> 3, f = idx & 7;
            float4 v4 = *(const float4*)(A + (size_t)(m0 + r) * lda + kb + f * 4);
            uint32_t off = (uint32_t)(r * 128 + f * 16);
            *(float4*)(dA + SMEM_SWIZZLE_128B(off)) = v4;
        }
        if (!TRANSB) {
            #pragma unroll
            for (int p = 0; p < NT / 16; p++) {
                int idx = t + p * 128;
                int r = idx >> 3, f = idx & 7;
                float4 v4 = *(const float4*)(B + (size_t)(n0 + r) * ldb + kb + f * 4);
                uint32_t off = (uint32_t)(r * 128 + f * 16);
                *(float4*)(dB + SMEM_SWIZZLE_128B(off)) = v4;
            }
        } else {
            constexpr int NF = NT / 4;
            #pragma unroll
            for (int p = 0; p < (32 * NF) / 128; p++) {
                int idx = t + p * 128;
                int kk = idx / NF, nf = idx - kk * NF;
                float4 v4 = *(const float4*)(B + (size_t)(kb + kk) * ldb + n0 + nf * 4);
                int nb = nf * 4;
                *(float*)(dB + SMEM_SWIZZLE_128B((uint32_t)((nb + 0) * 128 + kk * 4))) = v4.x;
                *(float*)(dB + SMEM_SWIZZLE_128B((uint32_t)((nb + 1) * 128 + kk * 4))) = v4.y;
                *(float*)(dB + SMEM_SWIZZLE_128B((uint32_t)((nb + 2) * 128 + kk * 4))) = v4.z;
                *(float*)(dB + SMEM_SWIZZLE_128B((uint32_t)((nb + 3) * 128 + kk * 4))) = v4.w;
            }
        }
        FENCE_PROXY_ASYNC_SHARED_CTA();
        __syncthreads();
        if (wid == 0) {
            if (elect_one_pred()) {
                #pragma unroll
                for (int ss = 0; ss < 4; ss++) {
                    mma_tf32_ss(tmem, adesc[st] + ss * 2, bdesc[st] + ss * 2, idesc,
                                (c > 0 || ss > 0) ? 1u : 0u);
                }
                TCGEN05_COMMIT(st ? mbar1 : mbar0);
            }
        }
    }
    // wait for last commit (commit observes all prior MMAs)
    if ((nchunk - 1) & 1) { MBARRIER_WAIT_PARITY(mbar1, ph1); }
    else                  { MBARRIER_WAIT_PARITY(mbar0, ph0); }

    TCGEN05_FENCE_AFTER();
    const int lid = t & 31;
    const int m = m0 + wid * 32 + lid;
    #pragma unroll
    for (int cb = 0; cb < NT; cb += 32) {
        uint32_t r[32];
        TCGEN05_LD_32X32B_X32(r, tmem + cb);
        TCGEN05_WAIT_LD();
        float* crow = C + (size_t)m * ldc + (n0 + cb);
        const float* erow = E ? (E + (size_t)m * lde + (n0 + cb)) : (const float*)0;
        #pragma unroll
        for (int j = 0; j < 32; j += 4) {
            float4 o;
            o.x = alpha * __uint_as_float(r[j + 0]);
            o.y = alpha * __uint_as_float(r[j + 1]);
            o.z = alpha * __uint_as_float(r[j + 2]);
            o.w = alpha * __uint_as_float(r[j + 3]);
            if (erow) {
                float4 e4 = *(const float4*)(erow + j);
                o.x += beta * e4.x; o.y += beta * e4.y;
                o.z += beta * e4.z; o.w += beta * e4.w;
            }
            *(float4*)(crow + j) = o;
        }
    }
    __syncthreads();
    if (t == 0) { MBARRIER_INVAL(mbar0); MBARRIER_INVAL(mbar1); }
    __syncthreads();
    if (wid == 0) TCGEN05_DEALLOC(tmem, NT);
#else
    __trap();
#endif
}

// ---------------- fused attn1 softmax + OA GEMM -------------------------------
// OA[m,:] = softmax(0.125 * q[m,:] @ KL^T) @ W   per (b,h).  N=256 fits in TMEM,
// so each thread owns a full score row -> exact per-thread softmax, P streamed
// back to SMEM in 32-col chunks and MMA'd against preloaded W.
__global__ void __launch_bounds__(128)
fused_attn1_k(const float* __restrict__ q)
{
#if HAS_TC
    extern __shared__ char dsm[];
    uint32_t base  = smem_to_u32(dsm);
    uint32_t a0 = (base + 1023u) & ~1023u;       // q chunk 0: 16KB
    uint32_t a1 = a0 + 16384;                    // q chunk 1: 16KB
    uint32_t b0 = a1 + 16384;                    // KL chunk 0: 32KB
    uint32_t b1 = b0 + 32768;                    // KL chunk 1: 32KB
    uint32_t wb = b1 + 32768;                    // W: 8 chunks x 8KB = 64KB
    uint32_t p0 = wb + 65536;                    // P buf 0: 16KB
    uint32_t p1 = p0 + 16384;                    // P buf 1: 16KB
    uint32_t aux = p1 + 16384;
    char* dA[2] = { dsm + (a0 - base), dsm + (a1 - base) };
    char* dB[2] = { dsm + (b0 - base), dsm + (b1 - base) };
    char* dW    = dsm + (wb - base);
    char* dP[2] = { dsm + (p0 - base), dsm + (p1 - base) };
    uint32_t tptr = aux, sbar = aux + 8, pm0 = aux + 16, pm1 = aux + 24;

    const int t = threadIdx.x, wid = t >> 5, lid = t & 31;
    const int bh = blockIdx.y, b = bh >> 3, h = bh & 7;
    const int m0 = blockIdx.x * 128;
    const float* qb = q + (size_t)b * ((size_t)NN_ * HH * DD) + (size_t)h * DD;
    const float* KLb = g_KL + (size_t)bh * MM * DD;
    const float* Wb  = g_W  + (size_t)bh * MM * DD;
    float* OAb = g_OA + (size_t)bh * NN_ * DD;

    if (wid == 0) TCGEN05_ALLOC(tptr, 512);
    if (t == 0) { MBARRIER_INIT(sbar, 1); MBARRIER_INIT(pm0, 1); MBARRIER_INIT(pm1, 1); }
    __syncthreads();
    uint32_t tmem;
    asm volatile("ld.shared.b32 %0, [%1];" : "=r"(tmem) : "r"(tptr));
    if (wid == 0) TCGEN05_RELINQUISH_ALLOC_PERMIT();
    const uint32_t D1 = tmem + 256;

    // ---- phase 0: load q tiles, KL tiles, W tiles ----
    #pragma unroll
    for (int kc = 0; kc < 2; kc++) {
        #pragma unroll
        for (int p = 0; p < 8; p++) {
            int idx = t + p * 128;
            int r = idx >> 3, f = idx & 7;
            float4 v4 = *(const float4*)(qb + (size_t)(m0 + r) * (HH * DD) + kc * 32 + f * 4);
            *(float4*)(dA[kc] + SMEM_SWIZZLE_128B((uint32_t)(r * 128 + f * 16))) = v4;
        }
        #pragma unroll
        for (int p = 0; p < 16; p++) {
            int idx = t + p * 128;
            int r = idx >> 3, f = idx & 7;
            float4 v4 = *(const float4*)(KLb + (size_t)r * DD + kc * 32 + f * 4);
            *(float4*)(dB[kc] + SMEM_SWIZZLE_128B((uint32_t)(r * 128 + f * 16))) = v4;
        }
    }
    #pragma unroll
    for (int cb = 0; cb < 8; cb++) {
        #pragma unroll
        for (int p = 0; p < 4; p++) {
            int idx = t + p * 128;
            int kk = idx >> 4, nf = idx & 15;
            float4 v4 = *(const float4*)(Wb + (size_t)(cb * 32 + kk) * DD + nf * 4);
            int nb = nf * 4;
            char* wchunk = dW + cb * 8192;
            *(float*)(wchunk + SMEM_SWIZZLE_128B((uint32_t)((nb + 0) * 128 + kk * 4))) = v4.x;
            *(float*)(wchunk + SMEM_SWIZZLE_128B((uint32_t)((nb + 1) * 128 + kk * 4))) = v4.y;
            *(float*)(wchunk + SMEM_SWIZZLE_128B((uint32_t)((nb + 2) * 128 + kk * 4))) = v4.z;
            *(float*)(wchunk + SMEM_SWIZZLE_128B((uint32_t)((nb + 3) * 128 + kk * 4))) = v4.w;
        }
    }
    FENCE_PROXY_ASYNC_SHARED_CTA();
    __syncthreads();

    // ---- phase 1: scores D0 = q @ KL^T  (128 x 256, K=64) ----
    const uint32_t idesc_s  = (1u << 4) | (2u << 7) | (2u << 10) | (32u << 17) | (8u << 24);
    const uint32_t idesc_oa = (1u << 4) | (2u << 7) | (2u << 10) | (8u  << 17) | (8u << 24);
    if (wid == 0) {
        if (elect_one_pred()) {
            #pragma unroll
            for (int kc = 0; kc < 2; kc++) {
                uint64_t ad = MAKE_SMEM_DESC(kc ? a1 : a0);
                uint64_t bd = MAKE_SMEM_DESC(kc ? b1 : b0);
                #pragma unroll
                for (int ss = 0; ss < 4; ss++)
                    mma_tf32_ss(tmem, ad + ss * 2, bd + ss * 2, idesc_s,
                                (kc > 0 || ss > 0) ? 1u : 0u);
            }
            TCGEN05_COMMIT(sbar);
        }
    }
    MBARRIER_WAIT_PARITY(sbar, 0);
    TCGEN05_FENCE_AFTER();

    // ---- phase 2: per-thread softmax over TMEM row + streamed P @ W ----
    // pass 1: row max (raw scores; scale 0.125 applied inside exp)
    float mxr = -1e30f;
    for (int cb = 0; cb < 8; cb++) {
        uint32_t r[32];
        TCGEN05_LD_32X32B_X32(r, tmem + cb * 32);
        TCGEN05_WAIT_LD();
        #pragma unroll
        for (int j = 0; j < 32; j++) mxr = fmaxf(mxr, __uint_as_float(r[j]));
    }
    // pass 2: exp, accumulate sum, stream P chunks through SMEM into MMA
    const int prow = wid * 32 + lid;      // this thread's tile row
    float sum = 0.f;
    int php0 = 0, php1 = 0;
    const uint64_t pdesc[2] = { MAKE_SMEM_DESC(p0), MAKE_SMEM_DESC(p1) };
    const uint64_t wdesc0 = MAKE_SMEM_DESC(wb);
    for (int cb = 0; cb < 8; cb++) {
        const int st = cb & 1;
        if (cb >= 2) {
            if (st) { MBARRIER_WAIT_PARITY(pm1, php1); php1 ^= 1; }
            else    { MBARRIER_WAIT_PARITY(pm0, php0); php0 ^= 1; }
        }
        uint32_t r[32];
        TCGEN05_LD_32X32B_X32(r, tmem + cb * 32);
        TCGEN05_WAIT_LD();
        float e[32];
        #pragma unroll
        for (int j = 0; j < 32; j++) {
            e[j] = __expf(0.125f * (__uint_as_float(r[j]) - mxr));
            sum += e[j];
        }
        char* P = dP[st];
        #pragma unroll
        for (int g = 0; g < 8; g++) {
            float4 v4 = make_float4(e[g*4], e[g*4+1], e[g*4+2], e[g*4+3]);
            *(float4*)(P + SMEM_SWIZZLE_128B((uint32_t)(prow * 128 + g * 16))) = v4;
        }
        FENCE_PROXY_ASYNC_SHARED_CTA();
        __syncthreads();
        if (wid == 0) {
            if (elect_one_pred()) {
                #pragma unroll
                for (int ss = 0; ss < 4; ss++)
                    mma_tf32_ss(D1, pdesc[st] + ss * 2, wdesc0 + cb * 512 + ss * 2,
                                idesc_oa, (cb > 0 || ss > 0) ? 1u : 0u);
                TCGEN05_COMMIT(st ? pm1 : pm0);
            }
        }
    }
    MBARRIER_WAIT_PARITY(pm1, php1);   // last chunk (cb=7) committed to pm1
    TCGEN05_FENCE_AFTER();

    // ---- epilogue: OA row = D1 row / sum ----
    const float inv = 1.0f / sum;
    float* orow = OAb + (size_t)(m0 + prow) * DD;
    #pragma unroll
    for (int cb = 0; cb < 2; cb++) {
        uint32_t r[32];
        TCGEN05_LD_32X32B_X32(r, D1 + cb * 32);
        TCGEN05_WAIT_LD();
        #pragma unroll
        for (int j = 0; j < 32; j += 4) {
            float4 o;
            o.x = inv * __uint_as_float(r[j + 0]);
            o.y = inv * __uint_as_float(r[j + 1]);
            o.z = inv * __uint_as_float(r[j + 2]);
            o.w = inv * __uint_as_float(r[j + 3]);
            *(float4*)(orow + cb * 32 + j) = o;
        }
    }
    __syncthreads();
    if (t == 0) { MBARRIER_INVAL(sbar); MBARRIER_INVAL(pm0); MBARRIER_INVAL(pm1); }
    __syncthreads();
    if (wid == 0) TCGEN05_DEALLOC(tmem, 512);
#else
    __trap();
#endif
}

// ---------------- register-resident row softmax ------------------------------
template<int C>
__global__ void softmax_reg_k(float* __restrict__ X)
{
    constexpr int V = C / 256;
    float* row = X + (size_t)blockIdx.x * C;
    int t = threadIdx.x;
    float v[V];
    float mx = -1e30f;
    #pragma unroll
    for (int i = 0; i < V; i++) { v[i] = row[t + i * 256]; mx = fmaxf(mx, v[i]); }
    __shared__ float red[256];
    red[t] = mx; __syncthreads();
    for (int s = 128; s > 0; s >>= 1) { if (t < s) red[t] = fmaxf(red[t], red[t + s]); __syncthreads(); }
    mx = red[0]; __syncthreads();
    float sum = 0.f;
    #pragma unroll
    for (int i = 0; i < V; i++) { v[i] = __expf(v[i] - mx); sum += v[i]; }
    red[t] = sum; __syncthreads();
    for (int s = 128; s > 0; s >>= 1) { if (t < s) red[t] += red[t + s]; __syncthreads(); }
    float inv = 1.0f / red[0];
    #pragma unroll
    for (int i = 0; i < V; i++) row[t + i * 256] = v[i] * inv;
}

// ---------------- pinv init ---------------------------------------------------
__global__ void colrow_max_k(const float* __restrict__ X)
{
    int bh = blockIdx.x, t = threadIdx.x;
    const float* xb = X + (size_t)bh * MM * MM;
    float cs = 0.f, rs = 0.f;
    for (int i = 0; i < MM; i++) cs += xb[(size_t)i * MM + t];
    for (int j = 0; j < MM; j++) rs += xb[(size_t)t * MM + j];
    __shared__ float rc[256], rr[256];
    rc[t] = cs; rr[t] = rs; __syncthreads();
    for (int s = 128; s > 0; s >>= 1) {
        if (t < s) { rc[t] = fmaxf(rc[t], rc[t + s]); rr[t] = fmaxf(rr[t], rr[t + s]); }
        __syncthreads();
    }
    if (t == 0) {
        atomicMax((int*)&g_scal[0], __float_as_int(rc[0]));
        atomicMax((int*)&g_scal[1], __float_as_int(rr[0]));
    }
}

__global__ void z0_k(const float* __restrict__ X, float* __restrict__ Z)
{
    __shared__ float tile[32][33];
    int bh = blockIdx.z;
    const float* xb = X + (size_t)bh * MM * MM;
    float* zb = Z + (size_t)bh * MM * MM;
    int i0 = blockIdx.x * 32, j0 = blockIdx.y * 32;
    tile[threadIdx.y][threadIdx.x] = xb[(size_t)(j0 + threadIdx.y) * MM + (i0 + threadIdx.x)];
    __syncthreads();
    float inv = 1.0f / (g_scal[0] * g_scal[1]);
    zb[(size_t)(i0 + threadIdx.y) * MM + (j0 + threadIdx.x)] = tile[threadIdx.x][threadIdx.y] * inv;
}

// ---------------- K-split reduce for G ---------------------------------------
__global__ void reduce_g_k(const float* __restrict__ Gp, float* __restrict__ G)
{
    int i = blockIdx.x * 256 + threadIdx.x;
    const size_t stride = (size_t)BH * MM * DD;
    float s = 0.f;
    #pragma unroll
    for (int p = 0; p < GSPLIT; p++) s += Gp[(size_t)p * stride + i];
    G[i] = s;
}

// ---------------- epilogue: depthwise conv + residual + transpose ------------
__global__ void epilogue_k(const float* __restrict__ v, const float* __restrict__ rw,
                           const float* __restrict__ OA, float* __restrict__ out)
{
    __shared__ float vt[96 * 64];
    __shared__ float w[KERN];
    int bh = blockIdx.y, b = bh >> 3, h = bh & 7;
    int i0 = blockIdx.x * 64;
    int t = threadIdx.x;
    if (t < KERN) w[t] = rw[h * KERN + t];
    #pragma unroll
    for (int p = 0; p < 6; p++) {
        int idx = t + p * 256;
        int r = idx >> 4, f = idx & 15;
        int ii = i0 - 16 + r;
        float4 val = make_float4(0.f, 0.f, 0.f, 0.f);
        if (ii >= 0 && ii < NN_)
            val = *(const float4*)(v + (((size_t)b * NN_ + ii) * HH + h) * DD + f * 4);
        *(float4*)(vt + r * 64 + f * 4) = val;
    }
    __syncthreads();
    int d4 = (t & 15) * 4;
    int irow = t >> 4;
    #pragma unroll
    for (int rr = 0; rr < 4; rr++) {
        int il = irow + rr * 16;
        int i = i0 + il;
        float4 acc = *(const float4*)(OA + ((size_t)bh * NN_ + i) * DD + d4);
        #pragma unroll
        for (int tap = 0; tap < KERN; tap++) {
            float4 vv = *(const float4*)(vt + (il + tap) * 64 + d4);
            float wt = w[tap];
            acc.x += vv.x * wt; acc.y += vv.y * wt;
            acc.z += vv.z * wt; acc.w += vv.w * wt;
        }
        *(float4*)(out + (((size_t)b * NN_ + i) * HH + h) * DD + d4) = acc;
    }
}

// ---------------- host side ---------------------------------------------------
static const size_t SHM_GEMM128 = 1024 + 2 * 16384 + 2 * 128 * 128 + 64;
static const size_t SHM_GEMM64  = 1024 + 2 * 16384 + 2 * 64 * 128 + 64;
static const size_t SHM_FUSED   = 1024 + 2 * 16384 + 2 * 32768 + 65536 + 2 * 16384 + 64;

static void tcg(bool transb, int NT,
                const float* A, size_t aso, size_t asi, int lda,
                const float* B, size_t bso, size_t bsi, int ldb,
                float* C, size_t cso, size_t csi, int ldc,
                const float* E, size_t eso, size_t esi, int lde,
                int M, int N, int K, int nsplit, size_t csplit,
                float alpha, float beta)
{
    dim3 g(N / NT, M / 128, BH * nsplit);
    if (NT == 128) {
        if (transb) tcgemm_k<128, true ><<<g, 128, SHM_GEMM128>>>(A, aso, asi, lda, B, bso, bsi, ldb, C, cso, csi, ldc, E, eso, esi, lde, K, nsplit, csplit, alpha, beta);
        else        tcgemm_k<128, false><<<g, 128, SHM_GEMM128>>>(A, aso, asi, lda, B, bso, bsi, ldb, C, cso, csi, ldc, E, eso, esi, lde, K, nsplit, csplit, alpha, beta);
    } else {
        if (transb) tcgemm_k<64, true ><<<g, 128, SHM_GEMM64>>>(A, aso, asi, lda, B, bso, bsi, ldb, C, cso, csi, ldc, E, eso, esi, lde, K, nsplit, csplit, alpha, beta);
        else        tcgemm_k<64, false><<<g, 128, SHM_GEMM64>>>(A, aso, asi, lda, B, bso, bsi, ldb, C, cso, csi, ldc, E, eso, esi, lde, K, nsplit, csplit, alpha, beta);
    }
}

extern "C" void kernel_launch(void* const* d_in, const int* in_sizes, int n_in,
                              void* d_out, int out_size)
{
    const float* q  = (const float*)d_in[0];
    const float* k  = (const float*)d_in[1];
    const float* v  = (const float*)d_in[2];
    const float* rw = (const float*)d_in[3];
    float* out = (float*)d_out;

    static bool attrs_set = false;
    if (!attrs_set) {
        cudaFuncSetAttribute(tcgemm_k<128, true >, cudaFuncAttributeMaxDynamicSharedMemorySize, (int)SHM_GEMM128);
        cudaFuncSetAttribute(tcgemm_k<128, false>, cudaFuncAttributeMaxDynamicSharedMemorySize, (int)SHM_GEMM128);
        cudaFuncSetAttribute(tcgemm_k<64,  true >, cudaFuncAttributeMaxDynamicSharedMemorySize, (int)SHM_GEMM64);
        cudaFuncSetAttribute(tcgemm_k<64,  false>, cudaFuncAttributeMaxDynamicSharedMemorySize, (int)SHM_GEMM64);
        cudaFuncSetAttribute(fused_attn1_k,        cudaFuncAttributeMaxDynamicSharedMemorySize, (int)SHM_FUSED);
        attrs_set = true;
    }

    float *QL, *KL, *X, *ZA, *ZB, *XZ, *T2, *T3, *S, *G, *Gp, *W, *OA;
    cudaGetSymbolAddress((void**)&QL, g_QL);
    cudaGetSymbolAddress((void**)&KL, g_KL);
    cudaGetSymbolAddress((void**)&X,  g_X);
    cudaGetSymbolAddress((void**)&ZA, g_ZA);
    cudaGetSymbolAddress((void**)&ZB, g_ZB);
    cudaGetSymbolAddress((void**)&XZ, g_XZ);
    cudaGetSymbolAddress((void**)&T2, g_T2);
    cudaGetSymbolAddress((void**)&T3, g_T3);
    cudaGetSymbolAddress((void**)&S,  g_S);
    cudaGetSymbolAddress((void**)&G,  g_G);
    cudaGetSymbolAddress((void**)&Gp, g_Gp);
    cudaGetSymbolAddress((void**)&W,  g_W);
    cudaGetSymbolAddress((void**)&OA, g_OA);

    const size_t LB  = (size_t)MM * DD;
    const size_t XB  = (size_t)MM * MM;
    const size_t SB  = (size_t)NN_ * MM;
    const size_t QSO = (size_t)NN_ * HH * DD;
    const size_t QSI = DD;
    const int    QLD = HH * DD;

    // launch 0: landmarks (also zeroes g_scal)
    landmarks_k<<<dim3(MM, BH), DD>>>(q, k);
    // launch 1: attn2 scores X = QL @ KL^T
    tcg(false, 128, QL, 8*LB, LB, DD,  KL, 8*LB, LB, DD,  X, 8*XB, XB, MM,
        nullptr, 0, 0, 0,  MM, MM, DD, 1, 0, 1.0f, 0.0f);
    // launch 2: softmax rows
    softmax_reg_k<MM><<<BH * MM, 256>>>(X);
    // launch 3-4: pinv init
    colrow_max_k<<<BH, 256>>>(X);
    z0_k<<<dim3(MM/32, MM/32, BH), dim3(32, 32)>>>(X, ZA);

    // launches 5..28: Newton-Schulz (launch 5 is the ncu-profiled one)
    for (int it = 0; it < 6; it++) {
        float* zc = (it & 1) ? ZB : ZA;
        float* zn = (it & 1) ? ZA : ZB;
        tcg(true, 128, X,  8*XB, XB, MM,  zc, 8*XB, XB, MM,  XZ, 8*XB, XB, MM,
            nullptr, 0, 0, 0,  MM, MM, MM, 1, 0, 1.0f, 0.0f);
        tcg(true, 128, XZ, 8*XB, XB, MM,  XZ, 8*XB, XB, MM,  T2, 8*XB, XB, MM,
            XZ, 8*XB, XB, MM,  MM, MM, MM, 1, 0, -1.0f, 7.0f);
        tcg(true, 128, XZ, 8*XB, XB, MM,  T2, 8*XB, XB, MM,  T3, 8*XB, XB, MM,
            XZ, 8*XB, XB, MM,  MM, MM, MM, 1, 0, -1.0f, 15.0f);
        tcg(true, 128, zc, 8*XB, XB, MM,  T3, 8*XB, XB, MM,  zn, 8*XB, XB, MM,
            zc, 8*XB, XB, MM,  MM, MM, MM, 1, 0, -0.25f, 3.25f);
    }
    // final z in ZA

    // attn3 scores: S[256,4096] = QL @ k^T
    tcg(false, 128, QL, 8*LB, LB, DD,  k, QSO, QSI, QLD,  S, 8*SB, SB, NN_,
        nullptr, 0, 0, 0,  MM, NN_, DD, 1, 0, 1.0f, 0.0f);
    softmax_reg_k<NN_><<<BH * MM, 256>>>(S);

    // G = S @ v  (K-split x8 + reduce)
    tcg(true, 64, S, 8*SB, SB, NN_,  v, QSO, QSI, QLD,  Gp, 8*LB, LB, DD,
        nullptr, 0, 0, 0,  MM, DD, NN_, GSPLIT, (size_t)BH * LB, 1.0f, 0.0f);
    reduce_g_k<<<(BH * MM * DD) / 256, 256>>>(Gp, G);

    // W = ZA @ G
    tcg(true, 64, ZA, 8*XB, XB, MM,  G, 8*LB, LB, DD,  W, 8*LB, LB, DD,
        nullptr, 0, 0, 0,  MM, DD, MM, 1, 0, 1.0f, 0.0f);

    // fused attn1 softmax + OA = softmax(0.125 q KL^T) @ W
    fused_attn1_k<<<dim3(NN_ / 128, BH), 128, SHM_FUSED>>>(q);

    // depthwise conv residual + transpose
    epilogue_k<<<dim3(NN_ / 64, BH), 256>>>(v, rw, OA, out);
}